// round 8
// baseline (speedup 1.0000x reference)
#include <cuda_runtime.h>

// waspGridSpatialIntegral: input [B=64, 2, W=512, W=512] fp32.
//   out[:,0,:,:] = cumsum(in[:,0,:,:], axis=-1)  (contiguous width)
//   out[:,1,:,:] = cumsum(in[:,1,:,:], axis=-2)  (height, stride W)
//
// 268 MB pure HBM streaming. One fused launch, 256-thread blocks:
//   blocks [0, 128)      : column scans, ch 1 (2 blocks/image, long pole first)
//   blocks [128, 128+4096): row scans, ch 0 (warp-per-row, 8 rows/block)
//
// R7: row path rebuilt. Old row path had 1 outstanding LDG.128/thread, a
// __syncthreads, and 32768 tiny blocks -> row stream was latency/overhead
// bound (why column-side pipelining never moved DRAM%). New row path:
// warp-per-row with cyclic float4 ownership -> 4 outstanding LDG.128/thread,
// zero smem, zero block barriers, 8x fewer blocks.

#define W      512
#define WW     (512 * 512)
#define B      64
#define NCOLB  (B * 2)              // 128 column blocks (256 cols each)
#define NROWB  (B * W / 8)          // 4096 row blocks (8 rows each)
#define UNR    32                   // column batch depth

__global__ __launch_bounds__(256) void wasp_integral_kernel(
    const float* __restrict__ in, float* __restrict__ out)
{
    const int bid = blockIdx.x;
    const int tid = threadIdx.x;

    if (bid < NCOLB) {
        // ------- channel 1: column scan (cumsum along y, stride W) -------
        const int b   = bid >> 1;
        const int col = (bid & 1) * 256 + tid;
        const float* src = in  + (size_t)(b * 2 + 1) * WW + col;
        float*       dst = out + (size_t)(b * 2 + 1) * WW + col;

        float acc = 0.0f;
        for (int r = 0; r < W; r += UNR) {
            float v[UNR];
            #pragma unroll
            for (int i = 0; i < UNR; ++i)               // 32 loads in flight
                v[i] = __ldcs(src + (size_t)(r + i) * W);
            #pragma unroll
            for (int i = 0; i < UNR; ++i) {
                acc += v[i];
                __stcs(dst + (size_t)(r + i) * W, acc);
            }
        }
    } else {
        // ------- channel 0: row scan, warp-per-row, cyclic float4 -------
        const int lane  = tid & 31;
        const int wid   = tid >> 5;                      // 0..7
        const int rowid = (bid - NCOLB) * 8 + wid;       // 0..32767
        const int b     = rowid >> 9;
        const int y     = rowid & 511;
        const size_t base = (size_t)(b * 2) * WW + (size_t)y * W;

        const float4* src = reinterpret_cast<const float4*>(in + base);
        float4*       dst = reinterpret_cast<float4*>(out + base);

        // cyclic ownership: thread owns float4 indices lane, lane+32, +64, +96
        float4 v[4];
        #pragma unroll
        for (int c = 0; c < 4; ++c)                      // 4 coalesced LDG.128
            v[c] = __ldcs(src + c * 32 + lane);

        float carry = 0.0f;
        #pragma unroll
        for (int c = 0; c < 4; ++c) {
            // local inclusive scan of this float4
            v[c].y += v[c].x; v[c].z += v[c].y; v[c].w += v[c].z;
            float s = v[c].w;                            // warp scan of totals
            #pragma unroll
            for (int d = 1; d < 32; d <<= 1) {
                float n = __shfl_up_sync(0xFFFFFFFFu, s, d);
                if (lane >= d) s += n;
            }
            const float off = carry + (s - v[c].w);      // exclusive prefix
            v[c].x += off; v[c].y += off; v[c].z += off; v[c].w += off;
            carry += __shfl_sync(0xFFFFFFFFu, s, 31);    // chunk-c total
        }

        #pragma unroll
        for (int c = 0; c < 4; ++c)                      // 4 coalesced STG.128
            __stcs(dst + c * 32 + lane, v[c]);
    }
}

extern "C" void kernel_launch(void* const* d_in, const int* in_sizes, int n_in,
                              void* d_out, int out_size)
{
    const float* in  = (const float*)d_in[0];
    float*       out = (float*)d_out;
    wasp_integral_kernel<<<NCOLB + NROWB, 256>>>(in, out);
}